// round 1
// baseline (speedup 1.0000x reference)
#include <cuda_runtime.h>

// ============================================================================
// EstimateCentroids: 9^3 binary erosion (separable, bit-packed) -> hash-binned
// integer segment sums (packed u64 shared atomics) -> centroids/boxes ->
// stable rank sort -> exact greedy NMS (suppression bitmask + warp scan).
// ============================================================================

#define XD 512
#define YD 512
#define ZD 48
#define NROWS (XD * YD)              // 262144
#define NVOX  (NROWS * ZD)           // 12582912
#define NBINS 4096
#define NWORDS 64                    // 4096/64

// ---------------- device scratch (static: no allocations allowed) -----------
__device__ unsigned long long g_zbits[NROWS];
__device__ unsigned long long g_ybits[NROWS];
__device__ unsigned long long g_xbits[NROWS];
__device__ unsigned long long g_acc1[NBINS];   // (sx+256c)<<32 | (sy+256c)
__device__ unsigned long long g_acc2[NBINS];   // (sz+256c)<<32 | c
__device__ float4 g_boxes[NBINS];
__device__ float4 g_bsort[NBINS];
__device__ int    g_scores[NBINS];
__device__ int    g_rank[NBINS];
__device__ int    g_order[NBINS];
__device__ unsigned long long g_clusterbits[NWORDS];
__device__ unsigned long long g_supmat[NBINS * NWORDS];
__device__ unsigned long long g_keepwords[NWORDS];

// ---------------- zero pass --------------------------------------------------
__global__ void zero_kernel() {
    int i = blockIdx.x * blockDim.x + threadIdx.x;
    if (i < NBINS) {
        g_acc1[i] = 0ULL;
        g_acc2[i] = 0ULL;
        g_rank[i] = 0;
    }
    if (i < NWORDS) g_clusterbits[i] = 0ULL;
}

// ---------------- erosion along z (and binarize) ----------------------------
// Block = 384 threads = 8 rows of 48 z-values, fully coalesced loads.
__global__ void erode_z_kernel(const float* __restrict__ pm) {
    __shared__ unsigned int bal[12];
    int tid = threadIdx.x;
    int gidx = blockIdx.x * 384 + tid;
    float v = pm[gidx];
    unsigned int m = __ballot_sync(0xFFFFFFFFu, v > 0.5f);
    if ((tid & 31) == 0) bal[tid >> 5] = m;
    __syncthreads();
    if (tid < 8) {
        const unsigned char* by = (const unsigned char*)bal;
        unsigned long long b = 0ULL;
        #pragma unroll
        for (int k = 0; k < 6; k++)
            b |= (unsigned long long)by[tid * 6 + k] << (8 * k);
        unsigned long long e = b;
        #pragma unroll
        for (int k = 1; k <= 4; k++)
            e &= (b >> k) & (b << k);
        e &= 0x0000FFFFFFFFFFFFULL;
        g_zbits[blockIdx.x * 8 + tid] = e;
    }
}

// ---------------- erosion along y -------------------------------------------
__global__ void erode_y_kernel() {
    int idx = blockIdx.x * blockDim.x + threadIdx.x;
    if (idx >= NROWS) return;
    int y = idx & (YD - 1);
    unsigned long long r;
    if (y < 4 || y > YD - 5) {
        r = 0ULL;
    } else {
        r = ~0ULL;
        #pragma unroll
        for (int dy = -4; dy <= 4; dy++)
            r &= g_zbits[idx + dy];
    }
    g_ybits[idx] = r;
}

// ---------------- erosion along x -------------------------------------------
__global__ void erode_x_kernel() {
    int idx = blockIdx.x * blockDim.x + threadIdx.x;
    if (idx >= NROWS) return;
    int x = idx >> 9;
    unsigned long long r;
    if (x < 4 || x > XD - 5) {
        r = 0ULL;
    } else {
        r = ~0ULL;
        #pragma unroll
        for (int dx = -4; dx <= 4; dx++)
            r &= g_ybits[idx + dx * YD];
    }
    g_xbits[idx] = r;
}

// ---------------- main accumulation -----------------------------------------
// One packed u64 shared atomic per valid voxel:
//   bits[48:64) = count(+1), [32:48) = x+256, [16:32) = y+256, [0:16) = z+256
#define ACC_BLOCKS 592
#define ACC_THREADS 512
__global__ void __launch_bounds__(ACC_THREADS) accum_kernel(const float* __restrict__ emb) {
    __shared__ unsigned long long sbins[NBINS];
    for (int i = threadIdx.x; i < NBINS; i += ACC_THREADS) sbins[i] = 0ULL;
    __syncthreads();

    const float* __restrict__ e0 = emb;
    const float* __restrict__ e1 = emb + NVOX;
    const float* __restrict__ e2 = emb + 2 * NVOX;

    int stride = gridDim.x * ACC_THREADS;
    for (int idx = blockIdx.x * ACC_THREADS + threadIdx.x; idx < NVOX; idx += stride) {
        unsigned int row = (unsigned int)idx / 48u;
        unsigned int z = (unsigned int)idx - row * 48u;
        if ((g_xbits[row] >> z) & 1ULL) {
            float a = e0[idx];
            float b = e1[idx];
            float c = e2[idx];
            if (a > -2.0f || b > -2.0f || c > -2.0f) {
                int cx = __float2int_rn(a * 25.0f);   // round-half-even == jnp.round
                int cy = __float2int_rn(b * 25.0f);
                int cz = __float2int_rn(c * 25.0f);
                unsigned int qx = (unsigned int)min(max(cx + 128, 0), 255);
                unsigned int qy = (unsigned int)min(max(cy + 128, 0), 255);
                unsigned int qz = (unsigned int)min(max(cz + 128, 0), 255);
                unsigned int h = qx * 73856093u ^ qy * 19349663u ^ qz * 83492791u;
                unsigned int seg = h & (NBINS - 1);
                unsigned long long p =
                    (1ULL << 48) |
                    ((unsigned long long)(unsigned int)(cx + 256) << 32) |
                    ((unsigned long long)(unsigned int)(cy + 256) << 16) |
                    (unsigned long long)(unsigned int)(cz + 256);
                atomicAdd(&sbins[seg], p);
            }
        }
    }
    __syncthreads();

    for (int i = threadIdx.x; i < NBINS; i += ACC_THREADS) {
        unsigned long long p = sbins[i];
        if (p) {
            unsigned long long cnt = p >> 48;
            unsigned long long xf = (p >> 32) & 0xFFFFULL;
            unsigned long long yf = (p >> 16) & 0xFFFFULL;
            unsigned long long zf = p & 0xFFFFULL;
            atomicAdd(&g_acc1[i], (xf << 32) | yf);
            atomicAdd(&g_acc2[i], (zf << 32) | cnt);
        }
    }
}

// ---------------- finalize: centroids, boxes, scores ------------------------
__global__ void finalize_kernel(float* __restrict__ out, int out_size) {
    int i = blockIdx.x * blockDim.x + threadIdx.x;
    if (i >= NBINS) return;
    unsigned long long a1 = g_acc1[i];
    unsigned long long a2 = g_acc2[i];
    int cnt = (int)(a2 & 0xFFFFFFFFULL);
    int sx = (int)(a1 >> 32) - 256 * cnt;
    int sy = (int)(a1 & 0xFFFFFFFFULL) - 256 * cnt;
    int sz = (int)(a2 >> 32) - 256 * cnt;
    float d = fmaxf((float)cnt, 1.0f);
    float c0 = (float)sx / d;
    float c1 = (float)sy / d;
    float c2 = (float)sz / d;
    if (i * 3 + 2 < out_size) {
        out[i * 3 + 0] = c0;
        out[i * 3 + 1] = c1;
        out[i * 3 + 2] = c2;
    }
    float4 bx;
    bx.x = c0 - 22.5f;
    bx.y = c1 - 22.5f;
    bx.z = c0 + 22.5f;
    bx.w = c1 + 22.5f;
    g_boxes[i] = bx;
    g_scores[i] = (cnt >= 10) ? cnt : -1;
}

// ---------------- rank counting: stable descending sort ---------------------
// rank(i) = #{j : s_j > s_i} + #{j : s_j == s_i && j < i}   (== jnp.argsort(-s))
__global__ void rank_kernel() {
    __shared__ int ss[256];
    int i = blockIdx.x * 256 + threadIdx.x;
    int jbase = blockIdx.y * 256;
    ss[threadIdx.x] = g_scores[jbase + threadIdx.x];
    int si = g_scores[i];
    __syncthreads();
    int r = 0;
    #pragma unroll 8
    for (int k = 0; k < 256; k++) {
        int sj = ss[k];
        int j = jbase + k;
        r += (sj > si) || (sj == si && j < i);
    }
    atomicAdd(&g_rank[i], r);
}

// ---------------- scatter into sorted order ---------------------------------
__global__ void scatter_kernel() {
    int i = blockIdx.x * blockDim.x + threadIdx.x;
    if (i >= NBINS) return;
    int r = g_rank[i];
    g_order[r] = i;
    g_bsort[r] = g_boxes[i];
    if (g_scores[i] >= 0)  // is_cluster (score == count >= 10, else -1)
        atomicOr(&g_clusterbits[r >> 6], 1ULL << (r & 63));
}

// ---------------- NMS suppression matrix ------------------------------------
// supmat[i][w] bit b set  <=>  j = w*64+b > i  and  IOU(b[i], b[j]) > 0.5
__global__ void nmsmat_kernel() {
    __shared__ float4 cb[64];
    int tid = threadIdx.x;
    int i = blockIdx.x * 64 + tid;
    cb[tid] = g_bsort[blockIdx.y * 64 + tid];
    __syncthreads();
    float4 bi = g_bsort[i];
    float a1 = (bi.z - bi.x) * (bi.w - bi.y);
    unsigned long long bits = 0ULL;
    #pragma unroll 4
    for (int t2 = 0; t2 < 64; t2++) {
        int j = blockIdx.y * 64 + t2;
        float4 bj = cb[t2];
        float xx1 = fmaxf(bi.x, bj.x);
        float yy1 = fmaxf(bi.y, bj.y);
        float xx2 = fminf(bi.z, bj.z);
        float yy2 = fminf(bi.w, bj.w);
        float inter = fmaxf(xx2 - xx1, 0.0f) * fmaxf(yy2 - yy1, 0.0f);
        float a2 = (bj.z - bj.x) * (bj.w - bj.y);
        float iou = inter / fmaxf(a1 + a2 - inter, 1e-9f);
        if (j > i && iou > 0.5f) bits |= 1ULL << t2;
    }
    g_supmat[i * NWORDS + blockIdx.y] = bits;
}

// ---------------- NMS sequential scan (single warp) -------------------------
__global__ void nmsscan_kernel() {
    int t = threadIdx.x;          // 32 threads; thread t owns remv words t, t+32
    unsigned long long r0 = 0ULL, r1 = 0ULL;
    for (int w = 0; w < NWORDS; w++) {
        unsigned long long cbw = g_clusterbits[w];
        unsigned long long rw = __shfl_sync(0xFFFFFFFFu,
                                            (w < 32) ? r0 : r1, w & 31);
        unsigned long long cand = cbw & ~rw;
        while (cand) {
            int b = __ffsll((long long)cand) - 1;
            int i = (w << 6) + b;
            r0 |= g_supmat[i * NWORDS + t];
            r1 |= g_supmat[i * NWORDS + 32 + t];
            unsigned long long rw2 = __shfl_sync(0xFFFFFFFFu,
                                                 (w < 32) ? r0 : r1, w & 31);
            cand &= ~rw2;
            cand &= ~(1ULL << b);
        }
        unsigned long long rf = __shfl_sync(0xFFFFFFFFu,
                                            (w < 32) ? r0 : r1, w & 31);
        if (t == 0) g_keepwords[w] = cbw & ~rf;
    }
}

// ---------------- write keep output ------------------------------------------
__global__ void keepout_kernel(float* __restrict__ out, int out_size) {
    int r = blockIdx.x * blockDim.x + threadIdx.x;
    if (r >= NBINS) return;
    int orig = g_order[r];
    unsigned long long kw = g_keepwords[r >> 6];
    float v = (float)((kw >> (r & 63)) & 1ULL);
    int pos = 3 * NBINS + orig;
    if (pos < out_size) out[pos] = v;
}

// ============================================================================
extern "C" void kernel_launch(void* const* d_in, const int* in_sizes, int n_in,
                              void* d_out, int out_size) {
    const float* emb = (const float*)d_in[0];   // (1,3,512,512,48) float32
    const float* pm  = (const float*)d_in[1];   // (1,1,512,512,48) float32
    float* out = (float*)d_out;

    zero_kernel<<<16, 256>>>();
    erode_z_kernel<<<NVOX / 384, 384>>>(pm);
    erode_y_kernel<<<NROWS / 256, 256>>>();
    erode_x_kernel<<<NROWS / 256, 256>>>();
    accum_kernel<<<ACC_BLOCKS, ACC_THREADS>>>(emb);
    finalize_kernel<<<16, 256>>>(out, out_size);
    rank_kernel<<<dim3(16, 16), 256>>>();
    scatter_kernel<<<16, 256>>>();
    nmsmat_kernel<<<dim3(64, 64), 64>>>();
    nmsscan_kernel<<<1, 32>>>();
    keepout_kernel<<<16, 256>>>(out, out_size);
}